// round 12
// baseline (speedup 1.0000x reference)
#include <cuda_runtime.h>
#include <cuda_fp16.h>

#define NN  50000
#define NE  1600000
#define INF 128
#define H   20
#define DH  64
#define CAP 128   // per-node edge bucket capacity (in-degree ~Poisson(32))

// ---------------- scratch (static __device__, no allocs) ----------------
__device__ float g_xw[NN * H];      // xw -> x1 (overwritten by k3)
__device__ float g_y[NN * H];       // y = xw * dinv
__device__ float g_deg[NN];         // dinv
__device__ int   g_cnt[NN];         // counts; ZERO invariant between runs (k3 restores)
__device__ int   g_srt[NN * CAP];   // bucketed src ids per dst node
// fp16 tables, packed 80B rows (5 uint4/row)
__device__ uint4 g_Trh[NN * 5];
__device__ uint4 g_Tch[NN * 5];
__device__ float g_cvec[2 * H];     // [c_mu | exp(c_var)] fp32
__device__ int   g_shift;           // 0 if edge_index int32, 1 if int64

static __device__ __forceinline__ int erow(const int* ei32, int e, int f) {
    return ei32[(long long)e << f];
}
static __device__ __forceinline__ int ecol(const int* ei32, int e, int f) {
    return ei32[(long long)(NE + e) << f];
}
static __device__ __forceinline__ float to_tf32(float x) {
    unsigned u;
    asm("cvt.rna.tf32.f32 %0, %1;" : "=r"(u) : "f"(x));
    return __uint_as_float(u);
}

// ---------------- KM: fused  xw = x @ W_gc  +  edge bucket fill --------------
// grid 6250 x 256 (NE = 6250*256 exactly). Blocks < 196 also handle 256 nodes.
#define NBLK_N ((NN + 255) / 256)   // 196
__global__ void __launch_bounds__(256)
kM_xw_fill(const float* __restrict__ x, const float* __restrict__ Wgc,
           const int* __restrict__ ei32) {
    __shared__ float Ws[INF * H];
    __shared__ int sShift;
    int tid = threadIdx.x;
    int bid = blockIdx.x;
    if (tid == 0) {
        int f = (ei32[1] == 0 && ei32[3] == 0 && ei32[5] == 0 && ei32[7] == 0) ? 1 : 0;
        sShift = f;
        if (bid == 0) g_shift = f;   // for k7
    }
    if (bid < NBLK_N) {
        for (int i = tid; i < INF * H; i += 256) Ws[i] = Wgc[i];
    }
    __syncthreads();
    int f = sShift;

    // ---- edge fill (all blocks) ----
    int e = bid * 256 + tid;
    int r = erow(ei32, e, f);
    int c = ecol(ei32, e, f);
    int pos = atomicAdd(&g_cnt[c], 1);
    if (pos < CAP) g_srt[c * CAP + pos] = r;

    // ---- node GEMV (blocks < 196) ----
    if (bid < NBLK_N) {
        int n = bid * 256 + tid;
        if (n < NN) {
            float acc[H];
#pragma unroll
            for (int k = 0; k < H; k++) acc[k] = 0.f;
            const float4* xr = (const float4*)(x + (size_t)n * INF);
#pragma unroll 4
            for (int i = 0; i < INF / 4; i++) {
                float4 v = xr[i];
                const float* w0 = &Ws[(4 * i) * H];
#pragma unroll
                for (int k = 0; k < H; k++) {
                    float a = fmaf(v.x, w0[k], acc[k]);
                    a = fmaf(v.y, w0[H + k], a);
                    a = fmaf(v.z, w0[2 * H + k], a);
                    acc[k] = fmaf(v.w, w0[3 * H + k], a);
                }
            }
#pragma unroll
            for (int k = 0; k < H; k++) g_xw[n * H + k] = acc[k];
        }
    }
}

// ---------------- K2b: dinv = rsqrt(cnt+1); y = xw*dinv ----------------
__global__ void k2b_y() {
    int n = blockIdx.x * blockDim.x + threadIdx.x;
    if (n >= NN) return;
    float dv = rsqrtf((float)g_cnt[n] + 1.0f);
    g_deg[n] = dv;
    const float4* xi = (const float4*)&g_xw[n * H];
    float4* yo = (float4*)&g_y[n * H];
#pragma unroll
    for (int q = 0; q < 5; q++) {
        float4 v = xi[q];
        v.x *= dv; v.y *= dv; v.z *= dv; v.w *= dv;
        yo[q] = v;
    }
}

// ---------------- K3: warp-per-node gather -> x1 (stored to g_xw); cvec ------
__global__ void __launch_bounds__(256)
k3_gx1(const float* __restrict__ bgc,
       const float* __restrict__ Wmu,
       const float* __restrict__ Wvar,
       const float* __restrict__ bmu,
       const float* __restrict__ bvar,
       const int* __restrict__ nid_p) {
    __shared__ float sb[H];
    for (int i = threadIdx.x; i < H; i += blockDim.x) sb[i] = bgc[i];
    __syncthreads();

    int n = blockIdx.x * 8 + (threadIdx.x >> 5);   // grid 6250*8 = 50000 exactly
    int lane = threadIdx.x & 31;

    int cnt = min(g_cnt[n], CAP);
    if (lane == 0) g_cnt[n] = 0;   // restore zero invariant for next run
    float dinv_n = g_deg[n];
    int base = n * CAP;

    float a0 = 0.f, a1 = 0.f, a2 = 0.f, a3 = 0.f;
    if (lane < H) a0 = g_y[n * H + lane];  // self-loop term y[n]
    int i = 0;
    for (; i + 4 <= cnt; i += 4) {
        int4 rr = *(const int4*)&g_srt[base + i];
        if (lane < H) {
            a0 += __ldg(&g_y[rr.x * H + lane]);
            a1 += __ldg(&g_y[rr.y * H + lane]);
            a2 += __ldg(&g_y[rr.z * H + lane]);
            a3 += __ldg(&g_y[rr.w * H + lane]);
        }
    }
    for (; i < cnt; i++) {
        int r0 = __ldg(&g_srt[base + i]);
        if (lane < H) a0 += __ldg(&g_y[r0 * H + lane]);
    }
    float agg = (a0 + a1) + (a2 + a3);

    float x1 = 0.f;
    if (lane < H) {
        x1 = fmaxf(fmaf(dinv_n, agg, sb[lane]), 0.f);
        g_xw[n * H + lane] = x1;   // x1 overwrites xw (xw dead after k2b)
    }

    if (n == nid_p[0] && lane < H) {
        float cm = bmu[lane], cv = bvar[lane];
#pragma unroll
        for (int j = 0; j < H; j++) {
            float xj = __shfl_sync(0x000fffffu, x1, j);
            cm = fmaf(xj, __ldg(&Wmu[(2 * H + j) * H + lane]), cm);
            cv = fmaf(xj, __ldg(&Wvar[(2 * H + j) * H + lane]), cv);
        }
        g_cvec[lane] = cm;
        g_cvec[H + lane] = expf(cv);
    }
}

// ---------------- K4: per-node tables via tf32 MMA  [128x24]@[24x80] ---------
#define ZS_STR 25
#define TB_STR 88
__global__ void __launch_bounds__(128)
k4_tab(const float* __restrict__ Wmu, const float* __restrict__ Wvar) {
    __shared__ float sA[128 * ZS_STR];   // x1 tile, tf32
    __shared__ float sB[24 * TB_STR];    // [Wmu_s|Wvar_s|Wmu_d|Wvar_d] tf32
    int tid = threadIdx.x;
    int nb = blockIdx.x * 128;
    int n = nb + tid;

    // x1 tile
    {
        float4 xr[5];
        if (n < NN) {
            const float4* p = (const float4*)&g_xw[n * H];
#pragma unroll
            for (int q = 0; q < 5; q++) xr[q] = p[q];
        } else {
#pragma unroll
            for (int q = 0; q < 5; q++) xr[q] = make_float4(0.f, 0.f, 0.f, 0.f);
        }
        float* row = &sA[tid * ZS_STR];
#pragma unroll
        for (int q = 0; q < 5; q++) {
            row[4 * q + 0] = to_tf32(xr[q].x);
            row[4 * q + 1] = to_tf32(xr[q].y);
            row[4 * q + 2] = to_tf32(xr[q].z);
            row[4 * q + 3] = to_tf32(xr[q].w);
        }
        row[20] = 0.f; row[21] = 0.f; row[22] = 0.f; row[23] = 0.f;
    }
    // W tile: cols 0-19 Wmu_src, 20-39 Wvar_src, 40-59 Wmu_dst, 60-79 Wvar_dst
    for (int i = tid; i < 24 * 80; i += 128) {
        int k = i / 80, col = i % 80;
        float v = 0.f;
        if (k < H) {
            if (col < 20)      v = Wmu[k * H + col];
            else if (col < 40) v = Wvar[k * H + (col - 20)];
            else if (col < 60) v = Wmu[(H + k) * H + (col - 40)];
            else               v = Wvar[(H + k) * H + (col - 60)];
        }
        sB[k * TB_STR + col] = to_tf32(v);
    }
    __syncthreads();

    int warp = tid >> 5, lane = tid & 31;
    int g = lane >> 2, t4 = lane & 3;

    float cfr[2][10][4];
#pragma unroll
    for (int m = 0; m < 2; m++)
#pragma unroll
        for (int nn = 0; nn < 10; nn++) {
            cfr[m][nn][0] = 0.f; cfr[m][nn][1] = 0.f;
            cfr[m][nn][2] = 0.f; cfr[m][nn][3] = 0.f;
        }

#pragma unroll
    for (int m = 0; m < 2; m++) {
        int rowbase = warp * 32 + m * 16;
#pragma unroll
        for (int k = 0; k < 3; k++) {
            unsigned a0 = __float_as_uint(sA[(rowbase + g)     * ZS_STR + k * 8 + t4]);
            unsigned a1 = __float_as_uint(sA[(rowbase + g + 8) * ZS_STR + k * 8 + t4]);
            unsigned a2 = __float_as_uint(sA[(rowbase + g)     * ZS_STR + k * 8 + t4 + 4]);
            unsigned a3 = __float_as_uint(sA[(rowbase + g + 8) * ZS_STR + k * 8 + t4 + 4]);
#pragma unroll
            for (int nn = 0; nn < 10; nn++) {
                unsigned b0 = __float_as_uint(sB[(k * 8 + t4)     * TB_STR + nn * 8 + g]);
                unsigned b1 = __float_as_uint(sB[(k * 8 + t4 + 4) * TB_STR + nn * 8 + g]);
                asm volatile(
                    "mma.sync.aligned.m16n8k8.row.col.f32.tf32.tf32.f32 "
                    "{%0,%1,%2,%3}, {%4,%5,%6,%7}, {%8,%9}, {%0,%1,%2,%3};"
                    : "+f"(cfr[m][nn][0]), "+f"(cfr[m][nn][1]),
                      "+f"(cfr[m][nn][2]), "+f"(cfr[m][nn][3])
                    : "r"(a0), "r"(a1), "r"(a2), "r"(a3), "r"(b0), "r"(b1));
            }
        }
    }

    // epilogue: exp on cols [20,40) and [60,80); fp16 half2 stores from frags
    __half* trh = (__half*)g_Trh;
    __half* tch = (__half*)g_Tch;
#pragma unroll
    for (int m = 0; m < 2; m++) {
#pragma unroll
        for (int nn = 0; nn < 10; nn++) {
            int cc = nn * 8 + 2 * t4;
            bool ex = (cc >= 20 && cc < 40) || (cc >= 60);
#pragma unroll
            for (int half_ = 0; half_ < 2; half_++) {
                int rowloc = warp * 32 + m * 16 + g + half_ * 8;
                int node = nb + rowloc;
                if (node < NN) {
                    float v0 = cfr[m][nn][2 * half_];
                    float v1 = cfr[m][nn][2 * half_ + 1];
                    if (ex) { v0 = __expf(v0); v1 = __expf(v1); }
                    __half2 hv = __floats2half2_rn(v0, v1);
                    if (cc < 40)
                        *(__half2*)&trh[(size_t)node * 40 + cc] = hv;
                    else
                        *(__half2*)&tch[(size_t)node * 40 + (cc - 40)] = hv;
                }
            }
        }
    }
}

// ---------------- K7: persistent blocks; noise staging + tf32 MMA ------------
#define WS_STR 72
#define NTILE (NE / 128)
#define K7_GRID 740
__global__ void __launch_bounds__(128)
k7_main(const int* __restrict__ ei32,
        const float* __restrict__ noise, const float* __restrict__ noise_u,
        const float* __restrict__ Wd1, const float* __restrict__ bd1,
        const float* __restrict__ wd2, const float* __restrict__ bd2_p,
        float* __restrict__ out) {
    __shared__ __align__(16) char buf[128 * ZS_STR * 4];
    __shared__ float sW[24 * WS_STR];
    __shared__ float sb1[DH];
    __shared__ float sw2[DH];
    __shared__ float scm[H];
    __shared__ float sev[H];
    __shared__ float sbd2;

    float* sNoise = (float*)buf;
    float* zs     = (float*)buf;

    int tid = threadIdx.x;
    for (int i = tid; i < 24 * DH; i += 128) {
        int k = i / DH, nn = i % DH;
        sW[k * WS_STR + nn] = (k < H) ? to_tf32(Wd1[k * DH + nn]) : 0.f;
    }
    if (tid < DH) { sb1[tid] = bd1[tid]; sw2[tid] = wd2[tid]; }
    if (tid < H)  { scm[tid] = g_cvec[tid]; sev[tid] = g_cvec[H + tid]; }
    if (tid == 0) sbd2 = bd2_p[0];
    __syncthreads();

    int f = g_shift;
    int warp = tid >> 5, lane = tid & 31;
    int g = lane >> 2, t4 = lane & 3;

    for (int tile = blockIdx.x; tile < NTILE; tile += K7_GRID) {
        {
            const float4* gn4 = (const float4*)(noise + (size_t)tile * 128 * H);
            float4* sn4 = (float4*)buf;
#pragma unroll
            for (int q = 0; q < 5; q++) sn4[q * 128 + tid] = gn4[q * 128 + tid];
        }

        int e = tile * 128 + tid;
        int r = erow(ei32, e, f);
        int c = ecol(ei32, e, f);

        union { uint4 u[5]; __half2 h[2 * H / 2]; } Ru, Cu;
        const uint4* trp = &g_Trh[r * 5];
        const uint4* tcp = &g_Tch[c * 5];
#pragma unroll
        for (int q = 0; q < 5; q++) { Ru.u[q] = trp[q]; Cu.u[q] = tcp[q]; }

        __syncthreads();

        union { float4 v[5]; float f[H]; } nz;
#pragma unroll
        for (int q = 0; q < 5; q++) nz.v[q] = *(const float4*)&sNoise[H * tid + 4 * q];

        float z[H];
#pragma unroll
        for (int j = 0; j < H / 2; j++) {
            float2 mr = __half22float2(Ru.h[j]);
            float2 mc = __half22float2(Cu.h[j]);
            float2 er = __half22float2(Ru.h[H / 2 + j]);
            float2 ec = __half22float2(Cu.h[H / 2 + j]);
            z[2 * j]     = (mr.x + mc.x + scm[2 * j])     + er.x * ec.x * sev[2 * j]     * nz.f[2 * j];
            z[2 * j + 1] = (mr.y + mc.y + scm[2 * j + 1]) + er.y * ec.y * sev[2 * j + 1] * nz.f[2 * j + 1];
        }
        __syncthreads();

#pragma unroll
        for (int j = 0; j < H; j++) zs[tid * ZS_STR + j] = to_tf32(z[j]);
        zs[tid * ZS_STR + 20] = 0.f;
        zs[tid * ZS_STR + 21] = 0.f;
        zs[tid * ZS_STR + 22] = 0.f;
        zs[tid * ZS_STR + 23] = 0.f;
        __syncthreads();

        float cfr[2][8][4];
#pragma unroll
        for (int m = 0; m < 2; m++)
#pragma unroll
            for (int n = 0; n < 8; n++) {
                float b0 = sb1[n * 8 + 2 * t4];
                float b1v = sb1[n * 8 + 2 * t4 + 1];
                cfr[m][n][0] = b0; cfr[m][n][1] = b1v;
                cfr[m][n][2] = b0; cfr[m][n][3] = b1v;
            }

#pragma unroll
        for (int m = 0; m < 2; m++) {
            int rowbase = warp * 32 + m * 16;
#pragma unroll
            for (int k = 0; k < 3; k++) {
                unsigned a0 = __float_as_uint(zs[(rowbase + g)     * ZS_STR + k * 8 + t4]);
                unsigned a1 = __float_as_uint(zs[(rowbase + g + 8) * ZS_STR + k * 8 + t4]);
                unsigned a2 = __float_as_uint(zs[(rowbase + g)     * ZS_STR + k * 8 + t4 + 4]);
                unsigned a3 = __float_as_uint(zs[(rowbase + g + 8) * ZS_STR + k * 8 + t4 + 4]);
#pragma unroll
                for (int n = 0; n < 8; n++) {
                    unsigned b0 = __float_as_uint(sW[(k * 8 + t4)     * WS_STR + n * 8 + g]);
                    unsigned b1 = __float_as_uint(sW[(k * 8 + t4 + 4) * WS_STR + n * 8 + g]);
                    asm volatile(
                        "mma.sync.aligned.m16n8k8.row.col.f32.tf32.tf32.f32 "
                        "{%0,%1,%2,%3}, {%4,%5,%6,%7}, {%8,%9}, {%0,%1,%2,%3};"
                        : "+f"(cfr[m][n][0]), "+f"(cfr[m][n][1]),
                          "+f"(cfr[m][n][2]), "+f"(cfr[m][n][3])
                        : "r"(a0), "r"(a1), "r"(a2), "r"(a3), "r"(b0), "r"(b1));
                }
            }
        }
        __syncthreads();

#pragma unroll
        for (int m = 0; m < 2; m++) {
            float p0 = 0.f, p1 = 0.f;
#pragma unroll
            for (int n = 0; n < 8; n++) {
                float w0 = sw2[n * 8 + 2 * t4];
                float w1 = sw2[n * 8 + 2 * t4 + 1];
                p0 = fmaf(fmaxf(cfr[m][n][0], 0.f), w0, p0);
                p0 = fmaf(fmaxf(cfr[m][n][1], 0.f), w1, p0);
                p1 = fmaf(fmaxf(cfr[m][n][2], 0.f), w0, p1);
                p1 = fmaf(fmaxf(cfr[m][n][3], 0.f), w1, p1);
            }
            p0 += __shfl_xor_sync(0xffffffffu, p0, 1);
            p0 += __shfl_xor_sync(0xffffffffu, p0, 2);
            p1 += __shfl_xor_sync(0xffffffffu, p1, 1);
            p1 += __shfl_xor_sync(0xffffffffu, p1, 2);
            if (t4 == 0) {
                int e0 = tile * 128 + warp * 32 + m * 16 + g;
                int e1 = e0 + 8;
                float sw_0 = fmaxf(p0 + sbd2, 0.f);
                float sw_1 = fmaxf(p1 + sbd2, 0.f);
                float u0 = noise_u[e0];
                float u1 = noise_u[e1];
                float eps0 = fmaf(-0.9998f, u0, 0.9999f);
                float ome0 = fmaf(0.9998f, u0, 0.0001f);
                float eps1 = fmaf(-0.9998f, u1, 0.9999f);
                float ome1 = fmaf(0.9998f, u1, 0.0001f);
                float gate0 = __logf(eps0) - __logf(ome0) + sw_0;
                float gate1 = __logf(eps1) - __logf(ome1) + sw_1;
                out[e0] = 1.0f / (1.0f + __expf(-gate0));
                out[e1] = 1.0f / (1.0f + __expf(-gate1));
            }
        }
    }
}

// ---------------- launcher ----------------
extern "C" void kernel_launch(void* const* d_in, const int* in_sizes, int n_in,
                              void* d_out, int out_size) {
    const float* x     = (const float*)d_in[0];
    const int*   ei32  = (const int*)d_in[1];
    const int*   nid   = (const int*)d_in[2];
    const float* noise = (const float*)d_in[3];
    const float* nu    = (const float*)d_in[4];
    const float* Wgc   = (const float*)d_in[5];
    const float* bgc   = (const float*)d_in[6];
    const float* Wmu   = (const float*)d_in[7];
    const float* bmu   = (const float*)d_in[8];
    const float* Wv    = (const float*)d_in[9];
    const float* bv    = (const float*)d_in[10];
    const float* Wd1   = (const float*)d_in[11];
    const float* bd1   = (const float*)d_in[12];
    const float* wd2   = (const float*)d_in[13];
    const float* bd2   = (const float*)d_in[14];
    float* out = (float*)d_out;

    kM_xw_fill<<<NE / 256, 256>>>(x, Wgc, ei32);
    k2b_y<<<(NN + 255) / 256, 256>>>();
    k3_gx1<<<NN / 8, 256>>>(bgc, Wmu, Wv, bmu, bv, nid);
    k4_tab<<<(NN + 127) / 128, 128>>>(Wmu, Wv);
    k7_main<<<K7_GRID, 128>>>(ei32, noise, nu, Wd1, bd1, wd2, bd2, out);
}

// round 13
// speedup vs baseline: 1.2378x; 1.2378x over previous
#include <cuda_runtime.h>
#include <cuda_fp16.h>

#define NN  50000
#define NE  1600000
#define INF 128
#define H   20
#define DH  64
#define CAP 128   // per-node edge bucket capacity (in-degree ~Poisson(32))

// ---------------- scratch (static __device__, no allocs) ----------------
__device__ float g_xw[NN * H];      // xw -> x1 (overwritten by k3)
__device__ float g_y[NN * H];       // y = xw * dinv
__device__ float g_deg[NN];         // dinv
__device__ int   g_cnt[NN];         // counts (zeroed by k1 each run)
__device__ int   g_srt[NN * CAP];   // bucketed src ids per dst node
// fp16 tables, packed 80B rows (5 uint4/row)
__device__ uint4 g_Trh[NN * 5];
__device__ uint4 g_Tch[NN * 5];
__device__ float g_cvec[2 * H];     // [c_mu | exp(c_var)] fp32
__device__ int   g_shift;           // 0 if edge_index int32, 1 if int64

static __device__ __forceinline__ int erow(const int* ei32, int e, int f) {
    return ei32[(long long)e << f];
}
static __device__ __forceinline__ int ecol(const int* ei32, int e, int f) {
    return ei32[(long long)(NE + e) << f];
}
static __device__ __forceinline__ float to_tf32(float x) {
    unsigned u;
    asm("cvt.rna.tf32.f32 %0, %1;" : "=r"(u) : "f"(x));
    return __uint_as_float(u);
}

// ---------------- K1: xw = x @ W_gc ; cnt init ; dtype detect ----------------
__global__ void k1_xw(const float* __restrict__ x, const float* __restrict__ Wgc,
                      const int* __restrict__ ei32) {
    __shared__ float Ws[INF * H];
    if (blockIdx.x == 0 && threadIdx.x == 0) {
        g_shift = (ei32[1] == 0 && ei32[3] == 0 && ei32[5] == 0 && ei32[7] == 0) ? 1 : 0;
    }
    for (int i = threadIdx.x; i < INF * H; i += blockDim.x) Ws[i] = Wgc[i];
    __syncthreads();
    int n = blockIdx.x * blockDim.x + threadIdx.x;
    if (n >= NN) return;
    float acc[H];
#pragma unroll
    for (int k = 0; k < H; k++) acc[k] = 0.f;
    const float4* xr = (const float4*)(x + (size_t)n * INF);
#pragma unroll 4
    for (int i = 0; i < INF / 4; i++) {
        float4 v = xr[i];
        const float* w0 = &Ws[(4 * i) * H];
#pragma unroll
        for (int k = 0; k < H; k++) {
            float a = fmaf(v.x, w0[k], acc[k]);
            a = fmaf(v.y, w0[H + k], a);
            a = fmaf(v.z, w0[2 * H + k], a);
            acc[k] = fmaf(v.w, w0[3 * H + k], a);
        }
    }
#pragma unroll
    for (int k = 0; k < H; k++) g_xw[n * H + k] = acc[k];
    g_cnt[n] = 0;
}

// ---------------- K2: single-pass bucket fill ----------------
__global__ void k2_fill(const int* __restrict__ ei32) {
    int e = blockIdx.x * blockDim.x + threadIdx.x;
    if (e >= NE) return;
    int f = g_shift;
    int r = erow(ei32, e, f);
    int c = ecol(ei32, e, f);
    int pos = atomicAdd(&g_cnt[c], 1);
    if (pos < CAP) g_srt[c * CAP + pos] = r;
}

// ---------------- K2b: dinv = rsqrt(cnt+1); y = xw*dinv ----------------
__global__ void k2b_y() {
    int n = blockIdx.x * blockDim.x + threadIdx.x;
    if (n >= NN) return;
    float dv = rsqrtf((float)g_cnt[n] + 1.0f);
    g_deg[n] = dv;
    const float4* xi = (const float4*)&g_xw[n * H];
    float4* yo = (float4*)&g_y[n * H];
#pragma unroll
    for (int q = 0; q < 5; q++) {
        float4 v = xi[q];
        v.x *= dv; v.y *= dv; v.z *= dv; v.w *= dv;
        yo[q] = v;
    }
}

// ---------------- K3: warp-per-node gather -> x1 (stored to g_xw); cvec ------
__global__ void __launch_bounds__(256)
k3_gx1(const float* __restrict__ bgc,
       const float* __restrict__ Wmu,
       const float* __restrict__ Wvar,
       const float* __restrict__ bmu,
       const float* __restrict__ bvar,
       const int* __restrict__ nid_p) {
    __shared__ float sb[H];
    for (int i = threadIdx.x; i < H; i += blockDim.x) sb[i] = bgc[i];
    __syncthreads();

    int n = blockIdx.x * 8 + (threadIdx.x >> 5);   // grid 6250*8 = 50000 exactly
    int lane = threadIdx.x & 31;

    int cnt = min(g_cnt[n], CAP);
    float dinv_n = g_deg[n];
    int base = n * CAP;

    float a0 = 0.f, a1 = 0.f, a2 = 0.f, a3 = 0.f;
    if (lane < H) a0 = g_y[n * H + lane];  // self-loop term y[n]
    int i = 0;
    for (; i + 4 <= cnt; i += 4) {
        int4 rr = *(const int4*)&g_srt[base + i];
        if (lane < H) {
            a0 += __ldg(&g_y[rr.x * H + lane]);
            a1 += __ldg(&g_y[rr.y * H + lane]);
            a2 += __ldg(&g_y[rr.z * H + lane]);
            a3 += __ldg(&g_y[rr.w * H + lane]);
        }
    }
    for (; i < cnt; i++) {
        int r0 = __ldg(&g_srt[base + i]);
        if (lane < H) a0 += __ldg(&g_y[r0 * H + lane]);
    }
    float agg = (a0 + a1) + (a2 + a3);

    float x1 = 0.f;
    if (lane < H) {
        x1 = fmaxf(fmaf(dinv_n, agg, sb[lane]), 0.f);
        g_xw[n * H + lane] = x1;   // x1 overwrites xw (xw dead after k2b)
    }

    if (n == nid_p[0] && lane < H) {
        float cm = bmu[lane], cv = bvar[lane];
#pragma unroll
        for (int j = 0; j < H; j++) {
            float xj = __shfl_sync(0x000fffffu, x1, j);
            cm = fmaf(xj, __ldg(&Wmu[(2 * H + j) * H + lane]), cm);
            cv = fmaf(xj, __ldg(&Wvar[(2 * H + j) * H + lane]), cv);
        }
        g_cvec[lane] = cm;
        g_cvec[H + lane] = expf(cv);
    }
}

// ---------------- K4: per-node tables via tf32 MMA  [128x24]@[24x80] ---------
#define ZS_STR 25
#define TB_STR 88
__global__ void __launch_bounds__(128)
k4_tab(const float* __restrict__ Wmu, const float* __restrict__ Wvar) {
    __shared__ float sA[128 * ZS_STR];   // x1 tile, tf32
    __shared__ float sB[24 * TB_STR];    // [Wmu_s|Wvar_s|Wmu_d|Wvar_d] tf32
    int tid = threadIdx.x;
    int nb = blockIdx.x * 128;
    int n = nb + tid;

    // x1 tile
    {
        float4 xr[5];
        if (n < NN) {
            const float4* p = (const float4*)&g_xw[n * H];
#pragma unroll
            for (int q = 0; q < 5; q++) xr[q] = p[q];
        } else {
#pragma unroll
            for (int q = 0; q < 5; q++) xr[q] = make_float4(0.f, 0.f, 0.f, 0.f);
        }
        float* row = &sA[tid * ZS_STR];
#pragma unroll
        for (int q = 0; q < 5; q++) {
            row[4 * q + 0] = to_tf32(xr[q].x);
            row[4 * q + 1] = to_tf32(xr[q].y);
            row[4 * q + 2] = to_tf32(xr[q].z);
            row[4 * q + 3] = to_tf32(xr[q].w);
        }
        row[20] = 0.f; row[21] = 0.f; row[22] = 0.f; row[23] = 0.f;
    }
    // W tile: cols 0-19 Wmu_src, 20-39 Wvar_src, 40-59 Wmu_dst, 60-79 Wvar_dst
    for (int i = tid; i < 24 * 80; i += 128) {
        int k = i / 80, col = i % 80;
        float v = 0.f;
        if (k < H) {
            if (col < 20)      v = Wmu[k * H + col];
            else if (col < 40) v = Wvar[k * H + (col - 20)];
            else if (col < 60) v = Wmu[(H + k) * H + (col - 40)];
            else               v = Wvar[(H + k) * H + (col - 60)];
        }
        sB[k * TB_STR + col] = to_tf32(v);
    }
    __syncthreads();

    int warp = tid >> 5, lane = tid & 31;
    int g = lane >> 2, t4 = lane & 3;

    float cfr[2][10][4];
#pragma unroll
    for (int m = 0; m < 2; m++)
#pragma unroll
        for (int nn = 0; nn < 10; nn++) {
            cfr[m][nn][0] = 0.f; cfr[m][nn][1] = 0.f;
            cfr[m][nn][2] = 0.f; cfr[m][nn][3] = 0.f;
        }

#pragma unroll
    for (int m = 0; m < 2; m++) {
        int rowbase = warp * 32 + m * 16;
#pragma unroll
        for (int k = 0; k < 3; k++) {
            unsigned a0 = __float_as_uint(sA[(rowbase + g)     * ZS_STR + k * 8 + t4]);
            unsigned a1 = __float_as_uint(sA[(rowbase + g + 8) * ZS_STR + k * 8 + t4]);
            unsigned a2 = __float_as_uint(sA[(rowbase + g)     * ZS_STR + k * 8 + t4 + 4]);
            unsigned a3 = __float_as_uint(sA[(rowbase + g + 8) * ZS_STR + k * 8 + t4 + 4]);
#pragma unroll
            for (int nn = 0; nn < 10; nn++) {
                unsigned b0 = __float_as_uint(sB[(k * 8 + t4)     * TB_STR + nn * 8 + g]);
                unsigned b1 = __float_as_uint(sB[(k * 8 + t4 + 4) * TB_STR + nn * 8 + g]);
                asm volatile(
                    "mma.sync.aligned.m16n8k8.row.col.f32.tf32.tf32.f32 "
                    "{%0,%1,%2,%3}, {%4,%5,%6,%7}, {%8,%9}, {%0,%1,%2,%3};"
                    : "+f"(cfr[m][nn][0]), "+f"(cfr[m][nn][1]),
                      "+f"(cfr[m][nn][2]), "+f"(cfr[m][nn][3])
                    : "r"(a0), "r"(a1), "r"(a2), "r"(a3), "r"(b0), "r"(b1));
            }
        }
    }

    // epilogue: exp on cols [20,40) and [60,80); fp16 half2 stores from frags
    __half* trh = (__half*)g_Trh;
    __half* tch = (__half*)g_Tch;
#pragma unroll
    for (int m = 0; m < 2; m++) {
#pragma unroll
        for (int nn = 0; nn < 10; nn++) {
            int cc = nn * 8 + 2 * t4;
            bool ex = (cc >= 20 && cc < 40) || (cc >= 60);
#pragma unroll
            for (int half_ = 0; half_ < 2; half_++) {
                int rowloc = warp * 32 + m * 16 + g + half_ * 8;
                int node = nb + rowloc;
                if (node < NN) {
                    float v0 = cfr[m][nn][2 * half_];
                    float v1 = cfr[m][nn][2 * half_ + 1];
                    if (ex) { v0 = __expf(v0); v1 = __expf(v1); }
                    __half2 hv = __floats2half2_rn(v0, v1);
                    if (cc < 40)
                        *(__half2*)&trh[(size_t)node * 40 + cc] = hv;
                    else
                        *(__half2*)&tch[(size_t)node * 40 + (cc - 40)] = hv;
                }
            }
        }
    }
}

// ---------------- K7: persistent blocks; noise staging + tf32 MMA ------------
#define WS_STR 72
#define NTILE (NE / 128)
#define K7_GRID 740
__global__ void __launch_bounds__(128)
k7_main(const int* __restrict__ ei32,
        const float* __restrict__ noise, const float* __restrict__ noise_u,
        const float* __restrict__ Wd1, const float* __restrict__ bd1,
        const float* __restrict__ wd2, const float* __restrict__ bd2_p,
        float* __restrict__ out) {
    __shared__ __align__(16) char buf[128 * ZS_STR * 4];
    __shared__ float sW[24 * WS_STR];
    __shared__ float sb1[DH];
    __shared__ float sw2[DH];
    __shared__ float scm[H];
    __shared__ float sev[H];
    __shared__ float sbd2;

    float* sNoise = (float*)buf;
    float* zs     = (float*)buf;

    int tid = threadIdx.x;
    for (int i = tid; i < 24 * DH; i += 128) {
        int k = i / DH, nn = i % DH;
        sW[k * WS_STR + nn] = (k < H) ? to_tf32(Wd1[k * DH + nn]) : 0.f;
    }
    if (tid < DH) { sb1[tid] = bd1[tid]; sw2[tid] = wd2[tid]; }
    if (tid < H)  { scm[tid] = g_cvec[tid]; sev[tid] = g_cvec[H + tid]; }
    if (tid == 0) sbd2 = bd2_p[0];
    __syncthreads();

    int f = g_shift;
    int warp = tid >> 5, lane = tid & 31;
    int g = lane >> 2, t4 = lane & 3;

    for (int tile = blockIdx.x; tile < NTILE; tile += K7_GRID) {
        {
            const float4* gn4 = (const float4*)(noise + (size_t)tile * 128 * H);
            float4* sn4 = (float4*)buf;
#pragma unroll
            for (int q = 0; q < 5; q++) sn4[q * 128 + tid] = gn4[q * 128 + tid];
        }

        int e = tile * 128 + tid;
        int r = erow(ei32, e, f);
        int c = ecol(ei32, e, f);

        union { uint4 u[5]; __half2 h[2 * H / 2]; } Ru, Cu;
        const uint4* trp = &g_Trh[r * 5];
        const uint4* tcp = &g_Tch[c * 5];
#pragma unroll
        for (int q = 0; q < 5; q++) { Ru.u[q] = trp[q]; Cu.u[q] = tcp[q]; }

        __syncthreads();

        union { float4 v[5]; float f[H]; } nz;
#pragma unroll
        for (int q = 0; q < 5; q++) nz.v[q] = *(const float4*)&sNoise[H * tid + 4 * q];

        float z[H];
#pragma unroll
        for (int j = 0; j < H / 2; j++) {
            float2 mr = __half22float2(Ru.h[j]);
            float2 mc = __half22float2(Cu.h[j]);
            float2 er = __half22float2(Ru.h[H / 2 + j]);
            float2 ec = __half22float2(Cu.h[H / 2 + j]);
            z[2 * j]     = (mr.x + mc.x + scm[2 * j])     + er.x * ec.x * sev[2 * j]     * nz.f[2 * j];
            z[2 * j + 1] = (mr.y + mc.y + scm[2 * j + 1]) + er.y * ec.y * sev[2 * j + 1] * nz.f[2 * j + 1];
        }
        __syncthreads();

#pragma unroll
        for (int j = 0; j < H; j++) zs[tid * ZS_STR + j] = to_tf32(z[j]);
        zs[tid * ZS_STR + 20] = 0.f;
        zs[tid * ZS_STR + 21] = 0.f;
        zs[tid * ZS_STR + 22] = 0.f;
        zs[tid * ZS_STR + 23] = 0.f;
        __syncthreads();

        float cfr[2][8][4];
#pragma unroll
        for (int m = 0; m < 2; m++)
#pragma unroll
            for (int n = 0; n < 8; n++) {
                float b0 = sb1[n * 8 + 2 * t4];
                float b1v = sb1[n * 8 + 2 * t4 + 1];
                cfr[m][n][0] = b0; cfr[m][n][1] = b1v;
                cfr[m][n][2] = b0; cfr[m][n][3] = b1v;
            }

#pragma unroll
        for (int m = 0; m < 2; m++) {
            int rowbase = warp * 32 + m * 16;
#pragma unroll
            for (int k = 0; k < 3; k++) {
                unsigned a0 = __float_as_uint(zs[(rowbase + g)     * ZS_STR + k * 8 + t4]);
                unsigned a1 = __float_as_uint(zs[(rowbase + g + 8) * ZS_STR + k * 8 + t4]);
                unsigned a2 = __float_as_uint(zs[(rowbase + g)     * ZS_STR + k * 8 + t4 + 4]);
                unsigned a3 = __float_as_uint(zs[(rowbase + g + 8) * ZS_STR + k * 8 + t4 + 4]);
#pragma unroll
                for (int n = 0; n < 8; n++) {
                    unsigned b0 = __float_as_uint(sW[(k * 8 + t4)     * WS_STR + n * 8 + g]);
                    unsigned b1 = __float_as_uint(sW[(k * 8 + t4 + 4) * WS_STR + n * 8 + g]);
                    asm volatile(
                        "mma.sync.aligned.m16n8k8.row.col.f32.tf32.tf32.f32 "
                        "{%0,%1,%2,%3}, {%4,%5,%6,%7}, {%8,%9}, {%0,%1,%2,%3};"
                        : "+f"(cfr[m][n][0]), "+f"(cfr[m][n][1]),
                          "+f"(cfr[m][n][2]), "+f"(cfr[m][n][3])
                        : "r"(a0), "r"(a1), "r"(a2), "r"(a3), "r"(b0), "r"(b1));
                }
            }
        }
        __syncthreads();

#pragma unroll
        for (int m = 0; m < 2; m++) {
            float p0 = 0.f, p1 = 0.f;
#pragma unroll
            for (int n = 0; n < 8; n++) {
                float w0 = sw2[n * 8 + 2 * t4];
                float w1 = sw2[n * 8 + 2 * t4 + 1];
                p0 = fmaf(fmaxf(cfr[m][n][0], 0.f), w0, p0);
                p0 = fmaf(fmaxf(cfr[m][n][1], 0.f), w1, p0);
                p1 = fmaf(fmaxf(cfr[m][n][2], 0.f), w0, p1);
                p1 = fmaf(fmaxf(cfr[m][n][3], 0.f), w1, p1);
            }
            p0 += __shfl_xor_sync(0xffffffffu, p0, 1);
            p0 += __shfl_xor_sync(0xffffffffu, p0, 2);
            p1 += __shfl_xor_sync(0xffffffffu, p1, 1);
            p1 += __shfl_xor_sync(0xffffffffu, p1, 2);
            if (t4 == 0) {
                int e0 = tile * 128 + warp * 32 + m * 16 + g;
                int e1 = e0 + 8;
                float sw_0 = fmaxf(p0 + sbd2, 0.f);
                float sw_1 = fmaxf(p1 + sbd2, 0.f);
                float u0 = noise_u[e0];
                float u1 = noise_u[e1];
                float eps0 = fmaf(-0.9998f, u0, 0.9999f);
                float ome0 = fmaf(0.9998f, u0, 0.0001f);
                float eps1 = fmaf(-0.9998f, u1, 0.9999f);
                float ome1 = fmaf(0.9998f, u1, 0.0001f);
                float gate0 = __logf(eps0) - __logf(ome0) + sw_0;
                float gate1 = __logf(eps1) - __logf(ome1) + sw_1;
                out[e0] = 1.0f / (1.0f + __expf(-gate0));
                out[e1] = 1.0f / (1.0f + __expf(-gate1));
            }
        }
    }
}

// ---------------- launcher ----------------
extern "C" void kernel_launch(void* const* d_in, const int* in_sizes, int n_in,
                              void* d_out, int out_size) {
    const float* x     = (const float*)d_in[0];
    const int*   ei32  = (const int*)d_in[1];
    const int*   nid   = (const int*)d_in[2];
    const float* noise = (const float*)d_in[3];
    const float* nu    = (const float*)d_in[4];
    const float* Wgc   = (const float*)d_in[5];
    const float* bgc   = (const float*)d_in[6];
    const float* Wmu   = (const float*)d_in[7];
    const float* bmu   = (const float*)d_in[8];
    const float* Wv    = (const float*)d_in[9];
    const float* bv    = (const float*)d_in[10];
    const float* Wd1   = (const float*)d_in[11];
    const float* bd1   = (const float*)d_in[12];
    const float* wd2   = (const float*)d_in[13];
    const float* bd2   = (const float*)d_in[14];
    float* out = (float*)d_out;

    k1_xw<<<(NN + 127) / 128, 128>>>(x, Wgc, ei32);
    k2_fill<<<(NE + 255) / 256, 256>>>(ei32);
    k2b_y<<<(NN + 255) / 256, 256>>>();
    k3_gx1<<<NN / 8, 256>>>(bgc, Wmu, Wv, bmu, bv, nid);
    k4_tab<<<(NN + 127) / 128, 128>>>(Wmu, Wv);
    k7_main<<<K7_GRID, 128>>>(ei32, noise, nu, Wd1, bd1, wd2, bd2, out);
}